// round 3
// baseline (speedup 1.0000x reference)
#include <cuda_runtime.h>
#include <cuda_bf16.h>
#include <cstdint>

#define B_ 1024
#define N_ 8192
#define K_ 4096

// Map: position j -> index into info_bits row, or -1 if frozen.
__device__ int g_map[N_];

// One wide kernel, one wave: every j binary-searches the sorted info_set.
__global__ __launch_bounds__(1024)
void build_map_kernel(const int* __restrict__ info_set) {
    const int j = blockIdx.x * 1024 + threadIdx.x;
    int lo = 0, hi = K_;
    while (lo < hi) {
        int mid = (lo + hi) >> 1;
        if (info_set[mid] < j) lo = mid + 1; else hi = mid;
    }
    g_map[j] = (lo < K_ && info_set[lo] == j) ? lo : -1;
}

__global__ __launch_bounds__(256)
void polar_kernel(const float* __restrict__ info_bits,
                  const int*   __restrict__ u_random,
                  float*       __restrict__ out)
{
    // Packed codeword: word (w*32 + L) holds elements
    // i = w*1024 + (L>>2)*128 + bit*4 + (L&3), bit = 0..31.
    __shared__ unsigned SW[256];

    const int b = blockIdx.x;
    const int t = threadIdx.x;
    const int w = t >> 5;
    const int l = t & 31;

    const int4*  ur4  = (const int4*)(u_random + (size_t)b * N_);
    const float* ib   = info_bits + (size_t)b * K_;
    const int4*  map4 = (const int4*)g_map;

    float* out_x = out;
    float* out_f = out + (size_t)1 * B_ * N_;
    float* out_u = out + (size_t)2 * B_ * N_;
    float* out_p = out + (size_t)3 * B_ * N_;   // (B,N,2)
    float* out_r = out + (size_t)5 * B_ * N_;   // (B,N,2)
    const size_t rb = (size_t)b * N_;

    // ---- Pass 0: constant p stores — zero dependencies, fire first ----
    {
        const float4 half4 = make_float4(0.5f, 0.5f, 0.5f, 0.5f);
        #pragma unroll
        for (int m = 0; m < 8; m++) {
            const int j0 = w * 1024 + m * 128 + l * 4;
            float4* pp = (float4*)(out_p + 2 * (rb + (size_t)j0));
            __stcs(pp + 0, half4);
            __stcs(pp + 1, half4);
        }
    }

    unsigned myword = 0;

    // ---- Pass 1: coalesced load, emit f/u/r, ballot-pack u bits ----
    #pragma unroll
    for (int m = 0; m < 8; m++) {
        const int j0 = w * 1024 + m * 128 + l * 4;
        const int4 ur = __ldcs(&ur4[j0 >> 2]);
        const int4 mp = map4[j0 >> 2];

        // All-select formulation: no I2F/F2I anywhere.
        const float urf0 = ur.x ? 1.0f : 0.0f;
        const float urf1 = ur.y ? 1.0f : 0.0f;
        const float urf2 = ur.z ? 1.0f : 0.0f;
        const float urf3 = ur.w ? 1.0f : 0.0f;

        const float uf0 = (mp.x >= 0) ? ib[mp.x] : urf0;
        const float uf1 = (mp.y >= 0) ? ib[mp.y] : urf1;
        const float uf2 = (mp.z >= 0) ? ib[mp.z] : urf2;
        const float uf3 = (mp.w >= 0) ? ib[mp.w] : urf3;

        const float ff0 = (mp.x >= 0) ? 2.0f : urf0;
        const float ff1 = (mp.y >= 0) ? 2.0f : urf1;
        const float ff2 = (mp.z >= 0) ? 2.0f : urf2;
        const float ff3 = (mp.w >= 0) ? 2.0f : urf3;

        const size_t o = rb + (size_t)j0;
        __stcs((float4*)(out_f + o), make_float4(ff0, ff1, ff2, ff3));
        __stcs((float4*)(out_u + o), make_float4(uf0, uf1, uf2, uf3));

        float4* rr = (float4*)(out_r + 2 * o);
        __stcs(rr + 0, make_float4(1.0f - urf0, urf0, 1.0f - urf1, urf1));
        __stcs(rr + 1, make_float4(1.0f - urf2, urf2, 1.0f - urf3, urf3));

        // u bit = (uf != 0): uf is exactly 0.0f or 1.0f.
        unsigned b0 = __ballot_sync(0xFFFFFFFFu, __float_as_int(uf0));
        unsigned b1 = __ballot_sync(0xFFFFFFFFu, __float_as_int(uf1));
        unsigned b2 = __ballot_sync(0xFFFFFFFFu, __float_as_int(uf2));
        unsigned b3 = __ballot_sync(0xFFFFFFFFu, __float_as_int(uf3));
        if ((l >> 2) == m) {
            const int e = l & 3;
            myword = (e == 0) ? b0 : (e == 1) ? b1 : (e == 2) ? b2 : b3;
        }
    }

    // ---- Butterfly (stages commute). Element index bits in this packing:
    //   bits 0..1  -> L&3, bits 2..6 -> bit-in-word, bits 7..9 -> L>>2,
    //   bits 10..12 -> warp id.
    unsigned o1;
    o1 = __shfl_xor_sync(0xFFFFFFFFu, myword, 1);  if (!(l & 1))  myword ^= o1;  // d=1
    o1 = __shfl_xor_sync(0xFFFFFFFFu, myword, 2);  if (!(l & 2))  myword ^= o1;  // d=2
    myword ^= (myword >> 1)  & 0x55555555u;                                      // d=4
    myword ^= (myword >> 2)  & 0x33333333u;                                      // d=8
    myword ^= (myword >> 4)  & 0x0F0F0F0Fu;                                      // d=16
    myword ^= (myword >> 8)  & 0x00FF00FFu;                                      // d=32
    myword ^= (myword >> 16) & 0x0000FFFFu;                                      // d=64
    o1 = __shfl_xor_sync(0xFFFFFFFFu, myword, 4);  if (!(l & 4))  myword ^= o1;  // d=128
    o1 = __shfl_xor_sync(0xFFFFFFFFu, myword, 8);  if (!(l & 8))  myword ^= o1;  // d=256
    o1 = __shfl_xor_sync(0xFFFFFFFFu, myword, 16); if (!(l & 16)) myword ^= o1;  // d=512

    SW[t] = myword;
    __syncthreads();
    if (!(w & 1)) SW[t] ^= SW[t + 32];   // d=1024
    __syncthreads();
    if (!(w & 2)) SW[t] ^= SW[t + 64];   // d=2048
    __syncthreads();
    if (!(w & 4)) SW[t] ^= SW[t + 128];  // d=4096
    __syncthreads();

    // ---- Pass 3: x[j] = packed_bit[brev13(j)], coalesced float4 stores ----
    #pragma unroll
    for (int m = 0; m < 8; m++) {
        const int j0 = m * 1024 + t * 4;                 // multiple of 4
        const unsigned i0 = __brev((unsigned)j0) >> 19;  // bits 11,12 zero
        const unsigned idx0 = ((i0 >> 10) << 5) | (((i0 >> 7) & 7) << 2) | (i0 & 3);
        const unsigned bit  = (i0 >> 2) & 31;
        // j bit0 -> i bit12 -> +128 words; j bit1 -> i bit11 -> +64 words
        const float x0 = ((SW[idx0]       >> bit) & 1u) ? 1.0f : 0.0f;
        const float x1 = ((SW[idx0 + 128] >> bit) & 1u) ? 1.0f : 0.0f;
        const float x2 = ((SW[idx0 + 64]  >> bit) & 1u) ? 1.0f : 0.0f;
        const float x3 = ((SW[idx0 + 192] >> bit) & 1u) ? 1.0f : 0.0f;
        __stcs((float4*)(out_x + rb + (size_t)j0), make_float4(x0, x1, x2, x3));
    }
}

extern "C" void kernel_launch(void* const* d_in, const int* in_sizes, int n_in,
                              void* d_out, int out_size) {
    const float* info_bits = (const float*)d_in[0];
    const int*   u_random  = (const int*)d_in[1];
    const int*   info_set  = (const int*)d_in[2];
    float* out = (float*)d_out;

    build_map_kernel<<<N_ / 1024, 1024>>>(info_set);
    polar_kernel<<<B_, 256>>>(info_bits, u_random, out);
}